// round 16
// baseline (speedup 1.0000x reference)
#include <cuda_runtime.h>
#include <math.h>

#define BB   512
#define MM   32
#define NAG  8
#define HH   256
#define KQ   64           // K quarter
#define NACT 16
#define HO   (HH * NAG)   // 2048
#define CT   512          // commout col-tile

#define ACT_OFF  0
#define BASE_OFF 8192
#define HID_OFF  8704
#define COMM_OFF 139776

__device__ float g_csum[BB * HH];
__device__ float g_part[4 * BB * HH];    // hid partials: one per kq (mats fused)
__device__ float g_cpart[4 * BB * HO];   // comm partials per kq
__device__ int   g_cnt[MM];              // zero at load; re-zeroed by k_commep
__device__ int   g_list[MM * BB];

__device__ __forceinline__ void cp_async16(void* smem_dst, const void* gsrc) {
    unsigned s = (unsigned)__cvta_generic_to_shared(smem_dst);
    asm volatile("cp.async.cg.shared.global [%0], [%1], 16;\n" :: "r"(s), "l"(gsrc));
}
#define CP_COMMIT() asm volatile("cp.async.commit_group;\n" ::: "memory")
#define CP_WAIT(n)  asm volatile("cp.async.wait_group %0;\n" :: "n"(n) : "memory")

// Per-example agent-sum + model-id grouping lists
__global__ void k_prep(const float* __restrict__ comm_in,
                       const int* __restrict__ mid) {
    int b = blockIdx.x;
    int h = threadIdx.x;
    const float* p = comm_in + b * NAG * HH + h;
    float s = 0.f;
#pragma unroll
    for (int a = 0; a < NAG; a++) s += p[a * HH];
    g_csum[b * HH + h] = s;
    if (h == 0) {
        int m = mid[b];
        int slot = atomicAdd(&g_cnt[m], 1);
        g_list[m * BB + slot] = b;
    }
}

// hid partial GEMM, both matrices fused (R14 form: simple batched weight loads).
// grid (32, 2 coltiles, 4 kq). 128 thr, 1 col/thread, 16-row chunks.
__global__ void __launch_bounds__(128) k_hidmm(
                      const float* __restrict__ prev_hid,
                      const float* __restrict__ Wc,
                      const float* __restrict__ Wr) {
    int m = blockIdx.x;
    int n = g_cnt[m];
    if (n == 0) return;
    int col = blockIdx.y * 128 + threadIdx.x;
    int kq  = blockIdx.z;

    const float* WcP = Wc + m * HH * HH + kq * KQ * HH + col;
    const float* WrP = Wr + m * HH * HH + kq * KQ * HH + col;
    const float* Xc  = g_csum + kq * KQ;
    const float* Xp  = prev_hid + kq * KQ;
    float* P = g_part + kq * (BB * HH);

    __shared__ float xc[16][KQ];
    __shared__ float xp[16][KQ];
    __shared__ int   rows[16];

    for (int base = 0; base < n; base += 16) {
        int R = n - base; if (R > 16) R = 16;
        for (int f = threadIdx.x; f < 16 * (KQ / 4); f += 128) {
            int r  = f >> 4;
            int k4 = f & 15;
            int rr  = (r < R) ? r : 0;
            int row = g_list[m * BB + base + rr];
            *(float4*)&xc[r][k4 * 4] = *(const float4*)&Xc[row * HH + k4 * 4];
            *(float4*)&xp[r][k4 * 4] = *(const float4*)&Xp[row * HH + k4 * 4];
            if (k4 == 0) rows[r] = row;
        }
        __syncthreads();

        float acc[16];
#pragma unroll
        for (int r = 0; r < 16; r++) acc[r] = 0.f;

        for (int k = 0; k < KQ; k += 8) {
            float wc[8], wr[8];
#pragma unroll
            for (int u = 0; u < 8; u++) {
                wc[u] = WcP[(k + u) * HH];
                wr[u] = WrP[(k + u) * HH];
            }
#pragma unroll
            for (int r = 0; r < 16; r++) {
#pragma unroll
                for (int u = 0; u < 8; u += 2) {
                    float2 c2 = *(const float2*)&xc[r][k + u];
                    float2 p2 = *(const float2*)&xp[r][k + u];
                    acc[r] = fmaf(c2.x, wc[u],     acc[r]);
                    acc[r] = fmaf(c2.y, wc[u + 1], acc[r]);
                    acc[r] = fmaf(p2.x, wr[u],     acc[r]);
                    acc[r] = fmaf(p2.y, wr[u + 1], acc[r]);
                }
            }
        }

        for (int r = 0; r < R; r++) P[rows[r] * HH + col] = acc[r];
        __syncthreads();
    }
}

// Fused: hid = tanh(sum of 4 partials + biases + lut); action softmax + baseline.
__global__ void __launch_bounds__(256) k_hidact(
                      const int* __restrict__ mid,
                      const float* __restrict__ bc, const float* __restrict__ br,
                      const float* __restrict__ lut, const int* __restrict__ inp,
                      const float* __restrict__ enc_bias,
                      const float* __restrict__ Wa, const float* __restrict__ ba,
                      const float* __restrict__ Wb, const float* __restrict__ bb,
                      float* __restrict__ hid,
                      float* __restrict__ act, float* __restrict__ base_out) {
    int b = blockIdx.x;
    int t = threadIdx.x;
    int m = mid[b];

    __shared__ float hsh[HH];
    __shared__ float sps[32 * 16];
    __shared__ float sb[8];

    {
        int c = t;
        float v = bc[m * HH + c] + br[m * HH + c]
                + enc_bias[c] + lut[inp[b] * HH + c];
#pragma unroll
        for (int s = 0; s < 4; s++) v += g_part[s * (BB * HH) + b * HH + c];
        float h = tanhf(v);
        hid[b * HH + c] = h;
        hsh[c] = h;
    }
    __syncthreads();

    if (t < 128) {
        int aq = t & 3;
        int kc = t >> 2;
        const float4* WaP = (const float4*)(Wa + m * HH * NACT + aq * 4);
        float4 a4 = make_float4(0.f, 0.f, 0.f, 0.f);
#pragma unroll
        for (int j = 0; j < 8; j++) {
            int k = kc * 8 + j;
            float4 w = WaP[k * 4];
            float x = hsh[k];
            a4.x += x * w.x; a4.y += x * w.y; a4.z += x * w.z; a4.w += x * w.w;
        }
        *(float4*)&sps[kc * 16 + aq * 4] = a4;
    }
    {
        const float* WbP = Wb + m * HH;
        float pv = hsh[t] * WbP[t];
#pragma unroll
        for (int o = 16; o > 0; o >>= 1) pv += __shfl_xor_sync(0xffffffffu, pv, o);
        if ((t & 31) == 0) sb[t >> 5] = pv;
    }
    __syncthreads();

    if (t < NACT) {
        float v = ba[m * NACT + t];
#pragma unroll
        for (int kc = 0; kc < 32; kc++) v += sps[kc * 16 + t];
        float mx = v;
#pragma unroll
        for (int o = 8; o > 0; o >>= 1) mx = fmaxf(mx, __shfl_xor_sync(0xffffu, mx, o, 16));
        float ev = expf(v - mx);
        float sum = ev;
#pragma unroll
        for (int o = 8; o > 0; o >>= 1) sum += __shfl_xor_sync(0xffffu, sum, o, 16);
        act[b * NACT + t] = ev / sum;
    }
    if (t == 0) {
        float s = 0.f;
#pragma unroll
        for (int i = 0; i < 8; i++) s += sb[i];
        base_out[b] = s + bb[m];
    }
}

// comm partial GEMM with cp.async double-buffered weight stages in smem.
// grid (32, 4 col-tiles of 512, 4 kq). 256 thr, 2 cols/thread, 16-row chunks.
// Weight stage = 8 k x 512 cols = 16KB; 2 stages in flight -> DRAM latency hidden.
__global__ void __launch_bounds__(256) k_commout(
                          const float* __restrict__ hid,
                          const float* __restrict__ Wo) {
    int m = blockIdx.x;
    int n = g_cnt[m];
    if (n == 0) return;
    int t    = threadIdx.x;
    int kq   = blockIdx.z;
    int col0 = blockIdx.y * CT + t * 2;

    __shared__ float hs[16][KQ];           // 4KB
    __shared__ float ws[2][8][CT];         // 32KB
    __shared__ int   rows[16];

    const float* WB = Wo + (size_t)m * HH * HO + (size_t)kq * KQ * HO + blockIdx.y * CT;
    float* P = g_cpart + (size_t)kq * BB * HO;

    for (int base = 0; base < n; base += 16) {
        int R = n - base; if (R > 16) R = 16;
        for (int f = t; f < 16 * (KQ / 4); f += 256) {
            int r  = f >> 4;
            int k4 = f & 15;
            int rr  = (r < R) ? r : 0;
            int row = g_list[m * BB + base + rr];
            *(float4*)&hs[r][k4 * 4] = *(const float4*)&hid[row * HH + kq * KQ + k4 * 4];
            if (k4 == 0) rows[r] = row;
        }

        // prefetch weight stage 0 (k rows 0..7)
#pragma unroll
        for (int i = 0; i < 4; i++) {
            int idx = t + i * 256;           // 1024 16B-copies per stage
            int k  = idx >> 7;
            int c4 = idx & 127;
            cp_async16(&ws[0][k][c4 * 4], WB + (size_t)k * HO + c4 * 4);
        }
        CP_COMMIT();

        float2 acc[16];
#pragma unroll
        for (int r = 0; r < 16; r++) { acc[r].x = 0.f; acc[r].y = 0.f; }

#pragma unroll
        for (int kb = 0; kb < 8; kb++) {
            int cur = kb & 1;
            if (kb < 7) {
                const float* src = WB + (size_t)(kb + 1) * 8 * HO;
#pragma unroll
                for (int i = 0; i < 4; i++) {
                    int idx = t + i * 256;
                    int k  = idx >> 7;
                    int c4 = idx & 127;
                    cp_async16(&ws[cur ^ 1][k][c4 * 4], src + (size_t)k * HO + c4 * 4);
                }
                CP_COMMIT();
                CP_WAIT(1);
            } else {
                CP_WAIT(0);
            }
            __syncthreads();   // stage `cur` fully landed (all threads)

            float2 w[8];
#pragma unroll
            for (int u = 0; u < 8; u++) w[u] = *(const float2*)&ws[cur][u][t * 2];
#pragma unroll
            for (int r = 0; r < 16; r++) {
                float xv[8];
                *(float4*)&xv[0] = *(const float4*)&hs[r][kb * 8];
                *(float4*)&xv[4] = *(const float4*)&hs[r][kb * 8 + 4];
#pragma unroll
                for (int u = 0; u < 8; u++) {
                    acc[r].x = fmaf(xv[u], w[u].x, acc[r].x);
                    acc[r].y = fmaf(xv[u], w[u].y, acc[r].y);
                }
            }
            __syncthreads();   // compute done before buffer `cur` is overwritten
        }

        for (int r = 0; r < R; r++) {
            int row = rows[r];
            *(float2*)(P + (size_t)row * HO + col0) = acc[r];
        }
        __syncthreads();
    }
}

// comm epilogue: comm = (p0+p1+p2+p3 + bo[m]) / 7; re-zeroes g_cnt for next replay.
__global__ void __launch_bounds__(256) k_commep(
                        const int* __restrict__ mid,
                        const float* __restrict__ bo,
                        float* __restrict__ comm) {
    int row  = blockIdx.x >> 1;
    int half = blockIdx.x & 1;
    int col  = half * (HO / 2) + threadIdx.x * 4;
    int m    = mid[row];

    size_t off = (size_t)row * HO + col;
    float4 p0 = *(const float4*)(g_cpart + off);
    float4 p1 = *(const float4*)(g_cpart + 1ull * BB * HO + off);
    float4 p2 = *(const float4*)(g_cpart + 2ull * BB * HO + off);
    float4 p3 = *(const float4*)(g_cpart + 3ull * BB * HO + off);
    float4 bv = *(const float4*)(bo + m * HO + col);
    float4 o;
    o.x = (p0.x + p1.x + p2.x + p3.x + bv.x) * (1.0f / 7.0f);
    o.y = (p0.y + p1.y + p2.y + p3.y + bv.y) * (1.0f / 7.0f);
    o.z = (p0.z + p1.z + p2.z + p3.z + bv.z) * (1.0f / 7.0f);
    o.w = (p0.w + p1.w + p2.w + p3.w + bv.w) * (1.0f / 7.0f);
    *(float4*)(comm + off) = o;

    if (blockIdx.x == 0 && threadIdx.x < MM) g_cnt[threadIdx.x] = 0;
}

extern "C" void kernel_launch(void* const* d_in, const int* in_sizes, int n_in,
                              void* d_out, int out_size) {
    const float* comm_in  = (const float*)d_in[0];
    const int*   inp      = (const int*)d_in[1];
    const float* prev_hid = (const float*)d_in[2];
    const int*   mid      = (const int*)d_in[4];
    const float* Wc       = (const float*)d_in[5];
    const float* bc       = (const float*)d_in[6];
    const float* Wr       = (const float*)d_in[7];
    const float* br       = (const float*)d_in[8];
    const float* Wa       = (const float*)d_in[9];
    const float* ba       = (const float*)d_in[10];
    const float* Wb       = (const float*)d_in[11];
    const float* bb       = (const float*)d_in[12];
    const float* Wo       = (const float*)d_in[13];
    const float* bo       = (const float*)d_in[14];
    const float* lut      = (const float*)d_in[15];
    const float* enc_bias = (const float*)d_in[16];

    float* out  = (float*)d_out;
    float* act  = out + ACT_OFF;
    float* base = out + BASE_OFF;
    float* hid  = out + HID_OFF;
    float* comm = out + COMM_OFF;

    k_prep<<<BB, HH>>>(comm_in, mid);
    k_hidmm<<<dim3(MM, 2, 4), 128>>>(prev_hid, Wc, Wr);
    k_hidact<<<BB, 256>>>(mid, bc, br, lut, inp, enc_bias,
                          Wa, ba, Wb, bb, hid, act, base);
    k_commout<<<dim3(MM, 4, 4), 256>>>(hid, Wo);
    k_commep<<<2 * BB, 256>>>(mid, bo, comm);
}

// round 17
// speedup vs baseline: 1.5159x; 1.5159x over previous
#include <cuda_runtime.h>
#include <math.h>
#include <stdint.h>

#define BB   512
#define MM   32
#define NAG  8
#define HH   256
#define KQ   64
#define NACT 16
#define HO   (HH * NAG)   // 2048

#define ACT_OFF  0
#define BASE_OFF 8192
#define HID_OFF  8704
#define COMM_OFF 139776

__device__ float g_csum[BB * HH];
__device__ float g_part[4 * BB * HH];    // hid partials: one per kq (mats fused)
__device__ int   g_cnt[MM];              // zero at load; re-zeroed by k_hidact
__device__ int   g_ncopy[MM];            // counts snapshot for k_commout
__device__ int   g_list[MM * BB];

// Per-example agent-sum + model-id grouping lists
__global__ void k_prep(const float* __restrict__ comm_in,
                       const int* __restrict__ mid) {
    int b = blockIdx.x;
    int h = threadIdx.x;
    const float* p = comm_in + b * NAG * HH + h;
    float s = 0.f;
#pragma unroll
    for (int a = 0; a < NAG; a++) s += p[a * HH];
    g_csum[b * HH + h] = s;
    if (h == 0) {
        int m = mid[b];
        int slot = atomicAdd(&g_cnt[m], 1);
        g_list[m * BB + slot] = b;
    }
}

// hid partial GEMM, both matrices fused (R14 form).
// grid (32, 2 coltiles, 4 kq). 128 thr, 1 col/thread, 16-row chunks.
__global__ void __launch_bounds__(128) k_hidmm(
                      const float* __restrict__ prev_hid,
                      const float* __restrict__ Wc,
                      const float* __restrict__ Wr) {
    int m = blockIdx.x;
    int n = g_cnt[m];
    if (n == 0) return;
    int col = blockIdx.y * 128 + threadIdx.x;
    int kq  = blockIdx.z;

    const float* WcP = Wc + m * HH * HH + kq * KQ * HH + col;
    const float* WrP = Wr + m * HH * HH + kq * KQ * HH + col;
    const float* Xc  = g_csum + kq * KQ;
    const float* Xp  = prev_hid + kq * KQ;
    float* P = g_part + kq * (BB * HH);

    __shared__ float xc[16][KQ];
    __shared__ float xp[16][KQ];
    __shared__ int   rows[16];

    for (int base = 0; base < n; base += 16) {
        int R = n - base; if (R > 16) R = 16;
        for (int f = threadIdx.x; f < 16 * (KQ / 4); f += 128) {
            int r  = f >> 4;
            int k4 = f & 15;
            int rr  = (r < R) ? r : 0;
            int row = g_list[m * BB + base + rr];
            *(float4*)&xc[r][k4 * 4] = *(const float4*)&Xc[row * HH + k4 * 4];
            *(float4*)&xp[r][k4 * 4] = *(const float4*)&Xp[row * HH + k4 * 4];
            if (k4 == 0) rows[r] = row;
        }
        __syncthreads();

        float acc[16];
#pragma unroll
        for (int r = 0; r < 16; r++) acc[r] = 0.f;

        for (int k = 0; k < KQ; k += 8) {
            float wc[8], wr[8];
#pragma unroll
            for (int u = 0; u < 8; u++) {
                wc[u] = WcP[(k + u) * HH];
                wr[u] = WrP[(k + u) * HH];
            }
#pragma unroll
            for (int r = 0; r < 16; r++) {
#pragma unroll
                for (int u = 0; u < 8; u += 2) {
                    float2 c2 = *(const float2*)&xc[r][k + u];
                    float2 p2 = *(const float2*)&xp[r][k + u];
                    acc[r] = fmaf(c2.x, wc[u],     acc[r]);
                    acc[r] = fmaf(c2.y, wc[u + 1], acc[r]);
                    acc[r] = fmaf(p2.x, wr[u],     acc[r]);
                    acc[r] = fmaf(p2.y, wr[u + 1], acc[r]);
                }
            }
        }

        for (int r = 0; r < R; r++) P[rows[r] * HH + col] = acc[r];
        __syncthreads();
    }
}

// Fused: hid = tanh(sum of 4 partials + biases + lut); action softmax + baseline.
// Block 0 also snapshots g_cnt -> g_ncopy and zeroes g_cnt for the next replay.
__global__ void __launch_bounds__(256) k_hidact(
                      const int* __restrict__ mid,
                      const float* __restrict__ bc, const float* __restrict__ br,
                      const float* __restrict__ lut, const int* __restrict__ inp,
                      const float* __restrict__ enc_bias,
                      const float* __restrict__ Wa, const float* __restrict__ ba,
                      const float* __restrict__ Wb, const float* __restrict__ bb,
                      float* __restrict__ hid,
                      float* __restrict__ act, float* __restrict__ base_out) {
    int b = blockIdx.x;
    int t = threadIdx.x;
    int m = mid[b];

    if (b == 0 && t < MM) {
        g_ncopy[t] = g_cnt[t];
        g_cnt[t] = 0;
    }

    __shared__ float hsh[HH];
    __shared__ float sps[32 * 16];
    __shared__ float sb[8];

    {
        int c = t;
        float v = bc[m * HH + c] + br[m * HH + c]
                + enc_bias[c] + lut[inp[b] * HH + c];
#pragma unroll
        for (int s = 0; s < 4; s++) v += g_part[s * (BB * HH) + b * HH + c];
        float h = tanhf(v);
        hid[b * HH + c] = h;
        hsh[c] = h;
    }
    __syncthreads();

    if (t < 128) {
        int aq = t & 3;
        int kc = t >> 2;
        const float4* WaP = (const float4*)(Wa + m * HH * NACT + aq * 4);
        float4 a4 = make_float4(0.f, 0.f, 0.f, 0.f);
#pragma unroll
        for (int j = 0; j < 8; j++) {
            int k = kc * 8 + j;
            float4 w = WaP[k * 4];
            float x = hsh[k];
            a4.x += x * w.x; a4.y += x * w.y; a4.z += x * w.z; a4.w += x * w.w;
        }
        *(float4*)&sps[kc * 16 + aq * 4] = a4;
    }
    {
        const float* WbP = Wb + m * HH;
        float pv = hsh[t] * WbP[t];
#pragma unroll
        for (int o = 16; o > 0; o >>= 1) pv += __shfl_xor_sync(0xffffffffu, pv, o);
        if ((t & 31) == 0) sb[t >> 5] = pv;
    }
    __syncthreads();

    if (t < NACT) {
        float v = ba[m * NACT + t];
#pragma unroll
        for (int kc = 0; kc < 32; kc++) v += sps[kc * 16 + t];
        float mx = v;
#pragma unroll
        for (int o = 8; o > 0; o >>= 1) mx = fmaxf(mx, __shfl_xor_sync(0xffffu, mx, o, 16));
        float ev = expf(v - mx);
        float sum = ev;
#pragma unroll
        for (int o = 8; o > 0; o >>= 1) sum += __shfl_xor_sync(0xffffu, sum, o, 16);
        act[b * NACT + t] = ev / sum;
    }
    if (t == 0) {
        float s = 0.f;
#pragma unroll
        for (int i = 0; i < 8; i++) s += sb[i];
        base_out[b] = s + bb[m];
    }
}

__device__ __forceinline__ uint32_t f2tf32(float x) {
    uint32_t r;
    asm("cvt.rna.tf32.f32 %0, %1;" : "=r"(r) : "f"(x));
    return r;
}

// comm_out via tf32 mma.m16n8k8, direct epilogue (bias + /7), no partials.
// grid (32, 16 col-tiles of 128). 256 thr = 8 warps x 2 n8-tiles.
// A = 16 hid rows staged as tf32 in smem; B = Wo fragments straight from gmem.
__global__ void __launch_bounds__(256) k_commout(
                          const float* __restrict__ hid,
                          const float* __restrict__ Wo,
                          const float* __restrict__ bo,
                          float* __restrict__ comm) {
    int m = blockIdx.x;
    int n = g_ncopy[m];
    if (n == 0) return;
    int t    = threadIdx.x;
    int w    = t >> 5;
    int lane = t & 31;
    int q    = lane & 3;   // threadID in group
    int g    = lane >> 2;  // group (0..7)
    int colbase = blockIdx.y * 128;

    __shared__ uint32_t As[16][260];   // tf32 A, padded stride (conflict-free frags)
    __shared__ int rows[16];

    const float* WoM = Wo + (size_t)m * HH * HO;

    // per-warp tile columns
    int n0a = colbase + (w * 2 + 0) * 8;
    int n0b = colbase + (w * 2 + 1) * 8;
    const float* Wt_a = WoM + (size_t)q * HO + n0a + g;
    const float* Wt_b = WoM + (size_t)q * HO + n0b + g;
    float2 bva = *(const float2*)&bo[m * HO + n0a + q * 2];
    float2 bvb = *(const float2*)&bo[m * HO + n0b + q * 2];

    for (int base = 0; base < n; base += 16) {
        int R = n - base; if (R > 16) R = 16;
        // stage 16 rows x 256 cols of hid as tf32
        for (int f = t; f < 16 * 64; f += 256) {
            int r  = f >> 6;
            int k4 = f & 63;
            int rr  = (r < R) ? r : 0;
            int row = g_list[m * BB + base + rr];
            float4 v = *(const float4*)&hid[row * HH + k4 * 4];
            uint4 u;
            u.x = f2tf32(v.x); u.y = f2tf32(v.y);
            u.z = f2tf32(v.z); u.w = f2tf32(v.w);
            *(uint4*)&As[r][k4 * 4] = u;
            if (k4 == 0 && r < R) rows[r] = row;
        }
        __syncthreads();

        float c0[4] = {0.f, 0.f, 0.f, 0.f};
        float c1[4] = {0.f, 0.f, 0.f, 0.f};

#pragma unroll 4
        for (int k8 = 0; k8 < 32; k8++) {
            int k0 = k8 * 8;
            uint32_t a0 = As[g][k0 + q];
            uint32_t a1 = As[g + 8][k0 + q];
            uint32_t a2 = As[g][k0 + q + 4];
            uint32_t a3 = As[g + 8][k0 + q + 4];

            float bf0a = Wt_a[(size_t)k0 * HO];
            float bf1a = Wt_a[(size_t)(k0 + 4) * HO];
            float bf0b = Wt_b[(size_t)k0 * HO];
            float bf1b = Wt_b[(size_t)(k0 + 4) * HO];
            uint32_t b0a = f2tf32(bf0a), b1a = f2tf32(bf1a);
            uint32_t b0b = f2tf32(bf0b), b1b = f2tf32(bf1b);

            asm volatile(
                "mma.sync.aligned.m16n8k8.row.col.f32.tf32.tf32.f32 "
                "{%0,%1,%2,%3}, {%4,%5,%6,%7}, {%8,%9}, {%0,%1,%2,%3};"
                : "+f"(c0[0]), "+f"(c0[1]), "+f"(c0[2]), "+f"(c0[3])
                : "r"(a0), "r"(a1), "r"(a2), "r"(a3), "r"(b0a), "r"(b1a));
            asm volatile(
                "mma.sync.aligned.m16n8k8.row.col.f32.tf32.tf32.f32 "
                "{%0,%1,%2,%3}, {%4,%5,%6,%7}, {%8,%9}, {%0,%1,%2,%3};"
                : "+f"(c1[0]), "+f"(c1[1]), "+f"(c1[2]), "+f"(c1[3])
                : "r"(a0), "r"(a1), "r"(a2), "r"(a3), "r"(b0b), "r"(b1b));
        }

        // writeback: rows g and g+8, cols n0+q*2, +1 per tile
        if (g < R) {
            int row = rows[g];
            float2 o;
            o.x = (c0[0] + bva.x) * (1.0f / 7.0f);
            o.y = (c0[1] + bva.y) * (1.0f / 7.0f);
            *(float2*)&comm[(size_t)row * HO + n0a + q * 2] = o;
            o.x = (c1[0] + bvb.x) * (1.0f / 7.0f);
            o.y = (c1[1] + bvb.y) * (1.0f / 7.0f);
            *(float2*)&comm[(size_t)row * HO + n0b + q * 2] = o;
        }
        if (g + 8 < R) {
            int row = rows[g + 8];
            float2 o;
            o.x = (c0[2] + bva.x) * (1.0f / 7.0f);
            o.y = (c0[3] + bva.y) * (1.0f / 7.0f);
            *(float2*)&comm[(size_t)row * HO + n0a + q * 2] = o;
            o.x = (c1[2] + bvb.x) * (1.0f / 7.0f);
            o.y = (c1[3] + bvb.y) * (1.0f / 7.0f);
            *(float2*)&comm[(size_t)row * HO + n0b + q * 2] = o;
        }
        __syncthreads();
    }
}

extern "C" void kernel_launch(void* const* d_in, const int* in_sizes, int n_in,
                              void* d_out, int out_size) {
    const float* comm_in  = (const float*)d_in[0];
    const int*   inp      = (const int*)d_in[1];
    const float* prev_hid = (const float*)d_in[2];
    const int*   mid      = (const int*)d_in[4];
    const float* Wc       = (const float*)d_in[5];
    const float* bc       = (const float*)d_in[6];
    const float* Wr       = (const float*)d_in[7];
    const float* br       = (const float*)d_in[8];
    const float* Wa       = (const float*)d_in[9];
    const float* ba       = (const float*)d_in[10];
    const float* Wb       = (const float*)d_in[11];
    const float* bb       = (const float*)d_in[12];
    const float* Wo       = (const float*)d_in[13];
    const float* bo       = (const float*)d_in[14];
    const float* lut      = (const float*)d_in[15];
    const float* enc_bias = (const float*)d_in[16];

    float* out  = (float*)d_out;
    float* act  = out + ACT_OFF;
    float* base = out + BASE_OFF;
    float* hid  = out + HID_OFF;
    float* comm = out + COMM_OFF;

    k_prep<<<BB, HH>>>(comm_in, mid);
    k_hidmm<<<dim3(MM, 2, 4), 128>>>(prev_hid, Wc, Wr);
    k_hidact<<<BB, 256>>>(mid, bc, br, lut, inp, enc_bias,
                          Wa, ba, Wb, bb, hid, act, base);
    k_commout<<<dim3(MM, 16), 256>>>(hid, Wo, bo, comm);
}